// round 17
// baseline (speedup 1.0000x reference)
#include <cuda_runtime.h>
#include <math.h>

#define Bsz 128
#define Tsz 256
#define Lw  4
#define DCc 128
#define DWw 128
#define Hh  256
#define Vv  6000
#define NEGV -1e30f
#define PPSZ (Bsz * 16 * 128)

// ---------------- device global scratch (no allocations allowed) ----------------
__device__ float g_proj[Vv * Lw * DCc];                 // PROJ[ch][w][e]
__device__ float g_word[(size_t)Tsz * Bsz * Lw * DWw];  // word[t][b][w][e]
__device__ float g_su[Tsz * Bsz * Lw];                  // su[t][b][w]
__device__ float g_rh[8 * Bsz * Hh];                    // h ring [slot][b][u]
__device__ float g_rc[8 * Bsz * Hh];                    // c ring
__device__ float g_rp[8 * Bsz * DWw];                   // pred ring [slot][b][e]
__device__ __align__(16) float g_pp[2 * PPSZ];          // pred partials [buf][b][ug][e]
__device__ unsigned g_arr[8 * 32];                      // per-group barrier counters (padded)

__device__ __forceinline__ float sigm(float x) { return 1.0f / (1.0f + expf(-x)); }

// ---------------- 16-CTA group barrier (monotonic epoch; reset by k_init) ----------
__device__ __forceinline__ void gbar(unsigned* ctr, unsigned target) {
    __syncthreads();
    if (threadIdx.x == 0) {
        __threadfence();
        atomicAdd(ctr, 1u);
        volatile unsigned* p = ctr;
        while (*p < target) { }
        __threadfence();
    }
    __syncthreads();
}

// ---------------- PROJ table (148 blocks = 1 wave, 2 chars/iter, 4 accumulators) ----
__global__ void k_proj(const float* __restrict__ emb,
                       const float* __restrict__ rW,
                       const float* __restrict__ rb,
                       const float* __restrict__ cW,
                       const float* __restrict__ cb) {
    extern __shared__ float sm[];
    float* srW = sm;               // 16384
    float* scW = srW + 16384;      // 16384
    float* srb = scW + 16384;      // 128
    float* scb = srb + 128;        // 128
    float* se  = scb + 128;        // 256
    float* sh  = se + 256;         // 256
    const int tid = threadIdx.x;   // 256 threads
    const int e = tid & 127, half = tid >> 7;
    const int w = blockIdx.y;

    for (int i = tid; i < 16384; i += 256) {
        srW[i] = rW[w * 16384 + i];
        scW[i] = cW[i];
    }
    if (tid < 128) { srb[tid] = rb[w * 128 + tid]; scb[tid] = cb[tid]; }
    __syncthreads();

    const int base = blockIdx.x * 163;
    for (int ci = 0; ci < 82; ci++) {
        const int ch = base + ci * 2 + half;
        const bool ok = (ci * 2 + half < 163) && (ch < Vv);
        se[half * 128 + e] = ok ? emb[ch * 128 + e] : 0.0f;
        __syncthreads();
        const float* seh = se + half * 128;
        float a0 = srb[e], a1 = 0.f, a2 = 0.f, a3 = 0.f;
        #pragma unroll 8
        for (int d = 0; d < 128; d += 4) {
            a0 = fmaf(seh[d + 0], srW[(d + 0) * 128 + e], a0);
            a1 = fmaf(seh[d + 1], srW[(d + 1) * 128 + e], a1);
            a2 = fmaf(seh[d + 2], srW[(d + 2) * 128 + e], a2);
            a3 = fmaf(seh[d + 3], srW[(d + 3) * 128 + e], a3);
        }
        float g = (a0 + a1) + (a2 + a3);
        sh[half * 128 + e] = sigm(g) * seh[e];
        __syncthreads();
        const float* shh = sh + half * 128;
        float p0 = scb[e], p1 = 0.f, p2 = 0.f, p3 = 0.f;
        #pragma unroll 8
        for (int d = 0; d < 128; d += 4) {
            p0 = fmaf(shh[d + 0], scW[(d + 0) * 128 + e], p0);
            p1 = fmaf(shh[d + 1], scW[(d + 1) * 128 + e], p1);
            p2 = fmaf(shh[d + 2], scW[(d + 2) * 128 + e], p2);
            p3 = fmaf(shh[d + 3], scW[(d + 3) * 128 + e], p3);
        }
        float p = (p0 + p1) + (p2 + p3);
        if (ok) g_proj[(ch * Lw + w) * DCc + e] = tanhf(p);
        __syncthreads();
    }
}

// ---------------- word + su tables ----------------
__global__ void k_word(const int* __restrict__ chars, const float* __restrict__ U) {
    const int t = blockIdx.x, b = blockIdx.y, tid = threadIdx.x; // 128 threads
    const int lane = tid & 31, wid = tid >> 5;
    __shared__ int ch[4];
    __shared__ float red[4];
    if (tid < 4) {
        int ti = t - tid;
        ch[tid] = (ti >= 0) ? chars[b * Tsz + ti] : 0;
    }
    __syncthreads();
    const float inv[4] = {1.0f, 0.5f, 1.0f / 3.0f, 0.25f};
    const float uw = U[tid];
    #pragma unroll
    for (int w = 0; w < 4; w++) {
        float acc = 0.0f;
        for (int c = 0; c <= w; c++) acc += g_proj[(ch[c] * Lw + w) * DCc + tid];
        acc *= inv[w];
        g_word[(((size_t)t * Bsz + b) * Lw + w) * DWw + tid] = acc;
        float v = acc * uw;
        #pragma unroll
        for (int o = 16; o; o >>= 1) v += __shfl_xor_sync(0xffffffffu, v, o);
        if (lane == 0) red[wid] = v;
        __syncthreads();
        if (tid == 0) g_su[(t * Bsz + b) * Lw + w] = red[0] + red[1] + red[2] + red[3];
        __syncthreads();
    }
}

// ---------------- init: c1,h1,pred0; rings slots 4..7; pp buf0; barriers ------------
__global__ void k_init(const float* __restrict__ lk, const float* __restrict__ lb,
                       const float* __restrict__ pW, const float* __restrict__ pb,
                       const float* __restrict__ bos) {
    __shared__ float sh1[256], sc1[256], sp0[128];
    const int u = threadIdx.x;  // 256 threads
    const int b = blockIdx.x;
    float zi = lb[u], zj = lb[256 + u], zo = lb[768 + u];
    for (int d = 0; d < 128; d++) {
        float x = bos[d];
        const float* row = lk + d * 1024;
        zi = fmaf(x, row[u], zi);
        zj = fmaf(x, row[256 + u], zj);
        zo = fmaf(x, row[768 + u], zo);
    }
    float nc = sigm(zi) * tanhf(zj);      // c0 = 0
    float nh = tanhf(nc) * sigm(zo);
    sc1[u] = nc; sh1[u] = nh;
    __syncthreads();
    if (u < 128) {
        float p = pb[u];
        for (int q = 0; q < 256; q++) p = fmaf(sh1[q], pW[q * 128 + u], p);
        sp0[u] = tanhf(p);
    }
    __syncthreads();
    for (int s = 4; s < 8; s++) {
        g_rc[(s * Bsz + b) * Hh + u] = sc1[u];
        g_rh[(s * Bsz + b) * Hh + u] = sh1[u];
        if (u < 128) g_rp[(s * Bsz + b) * DWw + u] = sp0[u];
    }
    // pp buffer 0 for row b: partial[pg][e] = sum_{lu} h1[pg*16+lu] * pW[(pg*16+lu)*128+e]
    {
        const int pg = u >> 4, sub = u & 15;
        float a[8];
        #pragma unroll
        for (int j = 0; j < 8; j++) a[j] = 0.0f;
        for (int lu = 0; lu < 16; lu++) {
            float nv = sh1[pg * 16 + lu];
            const float* wr = &pW[(pg * 16 + lu) * 128 + sub * 8];
            #pragma unroll
            for (int j = 0; j < 8; j++) a[j] = fmaf(nv, wr[j], a[j]);
        }
        float* dst = &g_pp[((size_t)b * 16 + pg) * 128 + sub * 8];
        #pragma unroll
        for (int j = 0; j < 8; j++) dst[j] = a[j];
    }
    if (b == 0 && u < 8) g_arr[u * 32] = 0u;
}

// ---------------- persistent sequential kernel ----------------
// CTA b (bg=b>>4, ug=b&15): every CTA redundantly computes pred/scores/argmax for
// ALL 16 rows of its group (Phase A/B) -> best[] lives in local smem, NO P1->P2
// cross-CTA sync needed. Phase C: LSTM for 16 rows x units ug*16..+15 (4x8 warps).
// Phase D: pred partials for next step. ONE group barrier per step orders all
// cross-CTA traffic (g_pp, g_rh, g_rc, g_rp), same proven protocol as R5-R14.
__global__ void __launch_bounds__(256, 1) k_run(
    const float* __restrict__ lk, const float* __restrict__ lb,
    const float* __restrict__ pW, const float* __restrict__ pb,
    float* __restrict__ out) {
    extern __shared__ float sm[];
    float* swl      = sm;               // 24576: Wl[k][uu*4+g]
    float* spws     = swl + 24576;      // 2048: pW slice [lu][e]
    float* spredall = spws + 2048;      // 2048: pred[r][e] for 16 group rows
    float* snh      = spredall + 2048;  // 256
    float* sbias    = snh + 256;        // 64
    int*   sbest    = (int*)(sbias + 64); // 16

    const int tid = threadIdx.x;
    const int b = blockIdx.x;
    const int bg = b >> 4, ug = b & 15;
    const int lane = tid & 31, warp = tid >> 5;
    const int rt = warp >> 1;                      // row tile 0..3
    const int lrow = rt * 4 + (lane >> 3);         // 0..15
    const int lunit = (warp & 1) * 8 + (lane & 7); // 0..15
    const int bb = bg * 16 + lrow;
    const int unit = ug * 16 + lunit;
    const int r = tid >> 4, sub = tid & 15;        // Phase A/B roles
    const int arow = bg * 16 + r;

    for (int i = tid; i < 24576; i += 256) {
        int k = i >> 6, m = i & 63, u2 = m >> 2, g = m & 3;
        swl[i] = lk[k * 1024 + g * 256 + ug * 16 + u2];
    }
    for (int i = tid; i < 2048; i += 256) {
        int lu = i >> 7, ee = i & 127;
        spws[i] = pW[(ug * 16 + lu) * 128 + ee];
    }
    if (tid < 64) { int u2 = tid >> 2, g = tid & 3; sbias[tid] = lb[g * 256 + ug * 16 + u2]; }
    // per-thread pred bias chunk (8 floats)
    float pbv[8];
    #pragma unroll
    for (int j = 0; j < 8; j++) pbv[j] = pb[sub * 8 + j];
    __syncthreads();

    float* out_sc = out;
    float* out_wl = out + Bsz * Tsz;
    unsigned* bar = &g_arr[bg * 32];

    for (int t = 0; t < Tsz; t++) {
        const int slot1 = (t + 7) & 7;  // (t-1) mod 8
        // ========== Phase A: redundant pred assembly for all 16 group rows ========
        {
            const float* ppb = &g_pp[(size_t)(t & 1) * PPSZ + (size_t)arow * 2048 + sub * 8];
            float4 aA = make_float4(0.f, 0.f, 0.f, 0.f);
            float4 aB = make_float4(0.f, 0.f, 0.f, 0.f);
            #pragma unroll
            for (int u2 = 0; u2 < 16; u2++) {
                float4 vA = __ldcg((const float4*)(ppb + u2 * 128));
                float4 vB = __ldcg((const float4*)(ppb + u2 * 128 + 4));
                aA.x += vA.x; aA.y += vA.y; aA.z += vA.z; aA.w += vA.w;
                aB.x += vB.x; aB.y += vB.y; aB.z += vB.z; aB.w += vB.w;
            }
            float4 pA, pB;
            pA.x = tanhf(pbv[0] + aA.x); pA.y = tanhf(pbv[1] + aA.y);
            pA.z = tanhf(pbv[2] + aA.z); pA.w = tanhf(pbv[3] + aA.w);
            pB.x = tanhf(pbv[4] + aB.x); pB.y = tanhf(pbv[5] + aB.y);
            pB.z = tanhf(pbv[6] + aB.z); pB.w = tanhf(pbv[7] + aB.w);
            *(float4*)(spredall + r * 128 + sub * 8) = pA;
            *(float4*)(spredall + r * 128 + sub * 8 + 4) = pB;
            if (r == ug) {  // owner publishes its own row's pred into the global ring
                float* dst = &g_rp[(slot1 * Bsz + b) * DWw + sub * 8];
                __stcg((float4*)dst, pA);
                __stcg((float4*)(dst + 4), pB);
            }
        }
        __syncthreads();
        // ========== Phase B: scores + argmax for all 16 group rows ================
        {
            const float* sp8 = spredall + r * 128 + sub * 8;
            const float* wbase = &g_word[(((size_t)t * Bsz + arow) * Lw) * DWw + sub * 8];
            float s0, s1, s2, s3;
            {
                float4 wa = __ldcg((const float4*)(wbase));
                float4 wb = __ldcg((const float4*)(wbase + 4));
                s0 = sp8[0] * wa.x;
                s0 = fmaf(sp8[1], wa.y, s0); s0 = fmaf(sp8[2], wa.z, s0); s0 = fmaf(sp8[3], wa.w, s0);
                s0 = fmaf(sp8[4], wb.x, s0); s0 = fmaf(sp8[5], wb.y, s0);
                s0 = fmaf(sp8[6], wb.z, s0); s0 = fmaf(sp8[7], wb.w, s0);
            }
            {
                const float* ph = &g_rp[(((t - 2) & 7) * Bsz + arow) * DWw + sub * 8];
                float4 pa = __ldcg((const float4*)ph), pb4 = __ldcg((const float4*)(ph + 4));
                float4 wa = __ldcg((const float4*)(wbase + DWw)), wb = __ldcg((const float4*)(wbase + DWw + 4));
                s1 = pa.x * wa.x;
                s1 = fmaf(pa.y, wa.y, s1); s1 = fmaf(pa.z, wa.z, s1); s1 = fmaf(pa.w, wa.w, s1);
                s1 = fmaf(pb4.x, wb.x, s1); s1 = fmaf(pb4.y, wb.y, s1);
                s1 = fmaf(pb4.z, wb.z, s1); s1 = fmaf(pb4.w, wb.w, s1);
            }
            {
                const float* ph = &g_rp[(((t - 3) & 7) * Bsz + arow) * DWw + sub * 8];
                float4 pa = __ldcg((const float4*)ph), pb4 = __ldcg((const float4*)(ph + 4));
                float4 wa = __ldcg((const float4*)(wbase + 2 * DWw)), wb = __ldcg((const float4*)(wbase + 2 * DWw + 4));
                s2 = pa.x * wa.x;
                s2 = fmaf(pa.y, wa.y, s2); s2 = fmaf(pa.z, wa.z, s2); s2 = fmaf(pa.w, wa.w, s2);
                s2 = fmaf(pb4.x, wb.x, s2); s2 = fmaf(pb4.y, wb.y, s2);
                s2 = fmaf(pb4.z, wb.z, s2); s2 = fmaf(pb4.w, wb.w, s2);
            }
            {
                const float* ph = &g_rp[(((t - 4) & 7) * Bsz + arow) * DWw + sub * 8];
                float4 pa = __ldcg((const float4*)ph), pb4 = __ldcg((const float4*)(ph + 4));
                float4 wa = __ldcg((const float4*)(wbase + 3 * DWw)), wb = __ldcg((const float4*)(wbase + 3 * DWw + 4));
                s3 = pa.x * wa.x;
                s3 = fmaf(pa.y, wa.y, s3); s3 = fmaf(pa.z, wa.z, s3); s3 = fmaf(pa.w, wa.w, s3);
                s3 = fmaf(pb4.x, wb.x, s3); s3 = fmaf(pb4.y, wb.y, s3);
                s3 = fmaf(pb4.z, wb.z, s3); s3 = fmaf(pb4.w, wb.w, s3);
            }
            // half-warp (16-lane) reduction; offsets <16 never cross the row boundary
            #pragma unroll
            for (int o = 1; o < 16; o <<= 1) {
                s0 += __shfl_xor_sync(0xffffffffu, s0, o);
                s1 += __shfl_xor_sync(0xffffffffu, s1, o);
                s2 += __shfl_xor_sync(0xffffffffu, s2, o);
                s3 += __shfl_xor_sync(0xffffffffu, s3, o);
            }
            float4 su4 = __ldcg((const float4*)&g_su[(t * Bsz + arow) * Lw]);
            s0 = s0 + su4.x;
            s1 = (1 <= t) ? s1 + su4.y : NEGV;
            s2 = (2 <= t) ? s2 + su4.z : NEGV;
            s3 = (3 <= t) ? s3 + su4.w : NEGV;
            int best = 0; float bs = s0;
            if (s1 > bs) { bs = s1; best = 1; }
            if (s2 > bs) { bs = s2; best = 2; }
            if (s3 > bs) { bs = s3; best = 3; }
            if (sub == 0) sbest[r] = best;
            if (r == ug && sub == 0) {          // owner writes outputs for its row
                out_sc[b * Tsz + t] = bs;
                out_wl[b * Tsz + t] = (float)(best + 1);
            }
        }
        __syncthreads();
        // ========== Phase C: LSTM for 16 rows x 16 units (4x8 per warp) ===========
        {
            const int best = sbest[lrow];
            const int hs = (t - 1 - best) & 7;
            float zi = sbias[lunit * 4 + 0], zj = sbias[lunit * 4 + 1];
            float zf = sbias[lunit * 4 + 2], zo = sbias[lunit * 4 + 3];
            const float4* xw = (const float4*)&g_word[(((size_t)t * Bsz + bb) * Lw + best) * DWw];
            #pragma unroll 4
            for (int kq = 0; kq < 32; kq++) {
                float4 x4 = __ldcg(xw + kq);
                const float* w0 = &swl[(kq * 4) * 64 + lunit * 4];
                float4 a = *(const float4*)(w0);
                float4 c = *(const float4*)(w0 + 64);
                float4 d = *(const float4*)(w0 + 128);
                float4 e = *(const float4*)(w0 + 192);
                zi = fmaf(x4.x, a.x, zi); zj = fmaf(x4.x, a.y, zj); zf = fmaf(x4.x, a.z, zf); zo = fmaf(x4.x, a.w, zo);
                zi = fmaf(x4.y, c.x, zi); zj = fmaf(x4.y, c.y, zj); zf = fmaf(x4.y, c.z, zf); zo = fmaf(x4.y, c.w, zo);
                zi = fmaf(x4.z, d.x, zi); zj = fmaf(x4.z, d.y, zj); zf = fmaf(x4.z, d.z, zf); zo = fmaf(x4.z, d.w, zo);
                zi = fmaf(x4.w, e.x, zi); zj = fmaf(x4.w, e.y, zj); zf = fmaf(x4.w, e.z, zf); zo = fmaf(x4.w, e.w, zo);
            }
            const float4* hw = (const float4*)&g_rh[(hs * Bsz + bb) * Hh];
            #pragma unroll 4
            for (int kq = 0; kq < 64; kq++) {
                float4 x4 = __ldcg(hw + kq);
                const float* w0 = &swl[(128 + kq * 4) * 64 + lunit * 4];
                float4 a = *(const float4*)(w0);
                float4 c = *(const float4*)(w0 + 64);
                float4 d = *(const float4*)(w0 + 128);
                float4 e = *(const float4*)(w0 + 192);
                zi = fmaf(x4.x, a.x, zi); zj = fmaf(x4.x, a.y, zj); zf = fmaf(x4.x, a.z, zf); zo = fmaf(x4.x, a.w, zo);
                zi = fmaf(x4.y, c.x, zi); zj = fmaf(x4.y, c.y, zj); zf = fmaf(x4.y, c.z, zf); zo = fmaf(x4.y, c.w, zo);
                zi = fmaf(x4.z, d.x, zi); zj = fmaf(x4.z, d.y, zj); zf = fmaf(x4.z, d.z, zf); zo = fmaf(x4.z, d.w, zo);
                zi = fmaf(x4.w, e.x, zi); zj = fmaf(x4.w, e.y, zj); zf = fmaf(x4.w, e.z, zf); zo = fmaf(x4.w, e.w, zo);
            }
            float cp = __ldcg(&g_rc[(hs * Bsz + bb) * Hh + unit]);
            float nc = cp * sigm(zf) + sigm(zi) * tanhf(zj);
            float nh = tanhf(nc) * sigm(zo);
            const int ws = t & 7;
            __stcg(&g_rc[(ws * Bsz + bb) * Hh + unit], nc);
            __stcg(&g_rh[(ws * Bsz + bb) * Hh + unit], nh);
            snh[lrow * 16 + lunit] = nh;
        }
        __syncthreads();
        // ========== Phase D: pred partials for next step ==========================
        {
            const int pr = tid >> 4, p8 = tid & 15;
            float4 acA = make_float4(0.f, 0.f, 0.f, 0.f);
            float4 acB = make_float4(0.f, 0.f, 0.f, 0.f);
            #pragma unroll
            for (int u = 0; u < 16; u++) {
                float nv = snh[pr * 16 + u];
                float4 wa = *(const float4*)&spws[u * 128 + p8 * 8];
                float4 wb = *(const float4*)&spws[u * 128 + p8 * 8 + 4];
                acA.x = fmaf(nv, wa.x, acA.x); acA.y = fmaf(nv, wa.y, acA.y);
                acA.z = fmaf(nv, wa.z, acA.z); acA.w = fmaf(nv, wa.w, acA.w);
                acB.x = fmaf(nv, wb.x, acB.x); acB.y = fmaf(nv, wb.y, acB.y);
                acB.z = fmaf(nv, wb.z, acB.z); acB.w = fmaf(nv, wb.w, acB.w);
            }
            float* dst = &g_pp[(size_t)((t + 1) & 1) * PPSZ +
                               ((size_t)(bg * 16 + pr) * 16 + ug) * 128 + p8 * 8];
            __stcg((float4*)dst, acA);
            __stcg((float4*)(dst + 4), acB);
        }
        gbar(bar, (unsigned)(t + 1) * 16u);
    }
}

// ---------------- launch ----------------
static const int PROJ_SMEM = (16384 + 16384 + 128 + 128 + 256 + 256) * 4;
static const int RUN_SMEM  = (24576 + 2048 + 2048 + 256 + 64 + 16) * 4;

extern "C" void kernel_launch(void* const* d_in, const int* in_sizes, int n_in,
                              void* d_out, int out_size) {
    const int*   chars = (const int*)d_in[0];
    const float* emb   = (const float*)d_in[1];
    const float* rW    = (const float*)d_in[2];
    const float* rb    = (const float*)d_in[3];
    const float* cW    = (const float*)d_in[4];
    const float* cb    = (const float*)d_in[5];
    const float* lk    = (const float*)d_in[6];
    const float* lb    = (const float*)d_in[7];
    const float* pW    = (const float*)d_in[8];
    const float* pb    = (const float*)d_in[9];
    const float* U     = (const float*)d_in[10];
    const float* bos   = (const float*)d_in[11];

    cudaFuncSetAttribute(k_proj, cudaFuncAttributeMaxDynamicSharedMemorySize, PROJ_SMEM);
    cudaFuncSetAttribute(k_run,  cudaFuncAttributeMaxDynamicSharedMemorySize, RUN_SMEM);

    k_init<<<Bsz, 256>>>(lk, lb, pW, pb, bos);
    k_proj<<<dim3(37, 4), 256, PROJ_SMEM>>>(emb, rW, rb, cW, cb);
    k_word<<<dim3(Tsz, Bsz), 128>>>(chars, U);
    k_run<<<Bsz, 256, RUN_SMEM>>>(lk, lb, pW, pb, (float*)d_out);
}